// round 9
// baseline (speedup 1.0000x reference)
#include <cuda_runtime.h>
#include <cuda_bf16.h>
#include <cstdint>

#define N_TOK   32768
#define NBATCH  64
#define NPER    512
#define DQK     128
#define MF      256
#define DV      256
#define SP      72    /* bf16 row stride, 64-col tiles */
#define SP32    40    /* bf16 row stride, 32-col tiles (80B: conflict-free ldmatrix) */

#define INV_D4      0.29730177875068026f
#define INV_SQRT_M  0.0625f
#define EPS_PHI     1e-4f
#define EPS_NORM    1e-8f

// ---------------- scratch ----------------
__device__ uint16_t g_QpH [(size_t)N_TOK * MF], g_QpL [(size_t)N_TOK * MF];   // [tok][feat]
__device__ uint16_t g_KpTH[(size_t)MF * N_TOK], g_KpTL[(size_t)MF * N_TOK];   // Kp0^T [feat][tok]
__device__ uint16_t g_VTH [(size_t)DV * N_TOK], g_VTL [(size_t)DV * N_TOK];   // (s*V)^T [v][tok]
__device__ uint16_t g_omTH[(size_t)MF * DQK],   g_omTL[(size_t)MF * DQK];
__device__ uint16_t g_KVTH[(size_t)NBATCH * DV * MF], g_KVTL[(size_t)NBATCH * DV * MF];
__device__ float    g_rowmax[N_TOK];
__device__ float    g_bmax[512];                 // per 64-token tile
__device__ unsigned g_segmax[NBATCH];
__device__ float    g_W  [512 * MF];             // weighted Kp0 colsum per 64-tok tile
__device__ float    g_SVp[(size_t)512 * DV];     // unweighted V colsum per 64-tok tile

// ---------------- helpers ----------------
__device__ __forceinline__ uint32_t smem_u32(const void* p) {
    uint32_t a;
    asm("{ .reg .u64 t; cvta.to.shared.u64 t, %1; cvt.u32.u64 %0, t; }" : "=r"(a) : "l"(p));
    return a;
}
__device__ __forceinline__ void ldsm4(uint32_t* r, uint32_t a) {
    asm volatile("ldmatrix.sync.aligned.m8n8.x4.shared.b16 {%0,%1,%2,%3}, [%4];"
        : "=r"(r[0]), "=r"(r[1]), "=r"(r[2]), "=r"(r[3]) : "r"(a));
}
__device__ __forceinline__ void mma16816(float* c, const uint32_t* a, const uint32_t* b) {
    asm volatile("mma.sync.aligned.m16n8k16.row.col.f32.bf16.bf16.f32 "
        "{%0,%1,%2,%3}, {%4,%5,%6,%7}, {%8,%9}, {%0,%1,%2,%3};"
        : "+f"(c[0]), "+f"(c[1]), "+f"(c[2]), "+f"(c[3])
        : "r"(a[0]), "r"(a[1]), "r"(a[2]), "r"(a[3]), "r"(b[0]), "r"(b[1]));
}
__device__ __forceinline__ void split1(float v, uint16_t& h, uint16_t& l) {
    __nv_bfloat16 hh = __float2bfloat16(v);
    __nv_bfloat16 ll = __float2bfloat16(v - __bfloat162float(hh));
    h = __bfloat16_as_ushort(hh); l = __bfloat16_as_ushort(ll);
}
__device__ __forceinline__ void split_pair(float a, float b, uint32_t& hw, uint32_t& lw) {
    uint16_t h0, l0, h1, l1;
    split1(a, h0, l0); split1(b, h1, l1);
    hw = (uint32_t)h0 | ((uint32_t)h1 << 16);
    lw = (uint32_t)l0 | ((uint32_t)l1 << 16);
}
__device__ __forceinline__ float from2(uint16_t h, uint16_t l) {
    return __bfloat162float(__ushort_as_bfloat16(h)) + __bfloat162float(__ushort_as_bfloat16(l));
}
__device__ __forceinline__ unsigned f2o(float f) {
    unsigned u = __float_as_uint(f);
    return (u & 0x80000000u) ? ~u : (u | 0x80000000u);
}
__device__ __forceinline__ float o2f(unsigned u) {
    return (u & 0x80000000u) ? __uint_as_float(u & 0x7fffffffu) : __uint_as_float(~u);
}
__device__ __forceinline__ float warpMax(float v) {
#pragma unroll
    for (int o = 16; o > 0; o >>= 1) v = fmaxf(v, __shfl_xor_sync(0xffffffffu, v, o));
    return v;
}
#define CP_COMMIT() asm volatile("cp.async.commit_group;" ::: "memory")
#define CP_WAIT0()  asm volatile("cp.async.wait_group 0;" ::: "memory")
#define CP_WAIT1()  asm volatile("cp.async.wait_group 1;" ::: "memory")

// stage ROWS x 64 u16 tile (stride SP) via cp.async, 256 threads
template <int ROWS>
__device__ __forceinline__ void stage_async(uint32_t sdst, const uint16_t* __restrict__ g,
                                            size_t stride, int tid)
{
    constexpr int ITER = ROWS * 8 / 256;
#pragma unroll
    for (int i = 0; i < ITER; i++) {
        int idx = i * 256 + tid;
        int r = idx >> 3, ck = idx & 7;
        uint32_t sa = sdst + (uint32_t)(r * SP * 2 + ck * 16);
        const void* ga = (const void*)(g + (size_t)r * stride + ck * 8);
        asm volatile("cp.async.cg.shared.global [%0], [%1], 16;" :: "r"(sa), "l"(ga));
    }
}
// stage 128 x 32 u16 tile (stride SP32) via cp.async, 256 threads
__device__ __forceinline__ void stage32(uint32_t sdst, const uint16_t* __restrict__ g,
                                        size_t stride, int tid)
{
#pragma unroll
    for (int i = 0; i < 2; i++) {
        int idx = i * 256 + tid;
        int r = idx >> 2, ck = idx & 3;
        uint32_t sa = sdst + (uint32_t)(r * SP32 * 2 + ck * 16);
        const void* ga = (const void*)(g + (size_t)r * stride + ck * 8);
        asm volatile("cp.async.cg.shared.global [%0], [%1], 16;" :: "r"(sa), "l"(ga));
    }
}

// ---------------- warp-tiled bf16x3 GEMM: one K chunk (NKS*16 wide) ----------------
template <int NKS, int SPAD>
__device__ __forceinline__ void gemm_chunk(float c[2][8][4],
    uint32_t Ahi, uint32_t Alo, uint32_t Bhi, uint32_t Blo, int lane, int m0, int n0)
{
    const uint32_t ao0 = (uint32_t)((m0 + (lane & 15)) * SPAD + (lane >> 4) * 8) * 2u;
    const uint32_t bo0 = (uint32_t)((n0 + ((lane >> 4) << 3) + (lane & 7)) * SPAD
                                    + ((lane >> 3) & 1) * 8) * 2u;
#pragma unroll
    for (int ks = 0; ks < NKS; ks++) {
        uint32_t ah[2][4], al[2][4];
        ldsm4(ah[0], Ahi + ao0 + ks * 32);
        ldsm4(ah[1], Ahi + ao0 + 16 * SPAD * 2 + ks * 32);
        ldsm4(al[0], Alo + ao0 + ks * 32);
        ldsm4(al[1], Alo + ao0 + 16 * SPAD * 2 + ks * 32);
#pragma unroll
        for (int n2 = 0; n2 < 4; n2++) {
            uint32_t bh[4], bl[4];
            ldsm4(bh, Bhi + bo0 + n2 * 16 * SPAD * 2 + ks * 32);
            ldsm4(bl, Blo + bo0 + n2 * 16 * SPAD * 2 + ks * 32);
#pragma unroll
            for (int mt = 0; mt < 2; mt++) {
                mma16816(c[mt][n2 * 2],     ah[mt], &bh[0]);
                mma16816(c[mt][n2 * 2],     al[mt], &bh[0]);
                mma16816(c[mt][n2 * 2],     ah[mt], &bl[0]);
                mma16816(c[mt][n2 * 2 + 1], ah[mt], &bh[2]);
                mma16816(c[mt][n2 * 2 + 1], al[mt], &bh[2]);
                mma16816(c[mt][n2 * 2 + 1], ah[mt], &bl[2]);
            }
        }
    }
}

// fragments -> f32 smem dbuf, row stride DS
template <int DS>
__device__ __forceinline__ void frag_to_dbuf(float* dbuf, const float c[2][8][4],
                                             int lane, int m0, int n0)
{
    int g = lane >> 2, j = lane & 3;
#pragma unroll
    for (int mt = 0; mt < 2; mt++)
#pragma unroll
        for (int nt = 0; nt < 8; nt++) {
            int r0 = m0 + mt * 16 + g, cc = n0 + nt * 8 + j * 2;
            dbuf[r0 * DS + cc]           = c[mt][nt][0];
            dbuf[r0 * DS + cc + 1]       = c[mt][nt][1];
            dbuf[(r0 + 8) * DS + cc]     = c[mt][nt][2];
            dbuf[(r0 + 8) * DS + cc + 1] = c[mt][nt][3];
        }
}

// ---------------- omega^T (4 CTAs) + segmax init ----------------
#define OMT_SMEM (128 * 65 * 4)
__global__ __launch_bounds__(256)
void omT_kernel(const float* __restrict__ omega) {
    extern __shared__ char smem[];
    float* tile = (float*)smem;                       // [128][65]
    const int tid = threadIdx.x;
    if (blockIdx.x == 0 && tid < NBATCH) g_segmax[tid] = 0u;
    const int m0 = blockIdx.x * 64;
#pragma unroll
    for (int i = 0; i < 32; i++) {
        int f = i * 256 + tid, k = f >> 6, mm = f & 63;
        tile[k * 65 + mm] = omega[k * MF + m0 + mm];
    }
    __syncthreads();
#pragma unroll
    for (int i = 0; i < 8; i++) {
        int f = i * 256 + tid, mm = f >> 5, kq = (f & 31) * 4;
        uint32_t h0, l0, h1, l1;
        split_pair(tile[kq * 65 + mm],       tile[(kq + 1) * 65 + mm], h0, l0);
        split_pair(tile[(kq + 2) * 65 + mm], tile[(kq + 3) * 65 + mm], h1, l1);
        *(uint2*)&g_omTH[(size_t)(m0 + mm) * DQK + kq] = make_uint2(h0, h1);
        *(uint2*)&g_omTL[(size_t)(m0 + mm) * DQK + kq] = make_uint2(l0, l1);
    }
}

// ---------------- vT: (s*V)^T planes + V colsum partials (64n x 128v tiles) ----------------
#define VT_SMEM (64 * 129 * 4 + 256)
__global__ __launch_bounds__(256)
void vT_kernel(const float* __restrict__ V) {
    extern __shared__ char smem[];
    float* tile = (float*)smem;                       // [64][129]
    float* s_sm = (float*)(smem + 64 * 129 * 4);      // [64]
    const int tid = threadIdx.x;
    const int nt = blockIdx.x, n0 = nt * 64, v0 = blockIdx.y * 128;
    if (tid < 64) s_sm[tid] = __expf(g_rowmax[n0 + tid] - o2f(g_segmax[n0 >> 9]));
#pragma unroll
    for (int i = 0; i < 32; i++) {
        int f = i * 256 + tid, n = f >> 7, v = f & 127;
        tile[n * 129 + v] = V[(size_t)(n0 + n) * DV + v0 + v];
    }
    __syncthreads();
#pragma unroll
    for (int i = 0; i < 8; i++) {
        int f = i * 256 + tid, v = f >> 4, nq = (f & 15) * 4;
        uint32_t h0, l0, h1, l1;
        split_pair(tile[nq * 129 + v] * s_sm[nq],
                   tile[(nq + 1) * 129 + v] * s_sm[nq + 1], h0, l0);
        split_pair(tile[(nq + 2) * 129 + v] * s_sm[nq + 2],
                   tile[(nq + 3) * 129 + v] * s_sm[nq + 3], h1, l1);
        *(uint2*)&g_VTH[(size_t)(v0 + v) * N_TOK + n0 + nq] = make_uint2(h0, h1);
        *(uint2*)&g_VTL[(size_t)(v0 + v) * N_TOK + n0 + nq] = make_uint2(l0, l1);
    }
    if (tid < 128) {
        float s = 0.f;
#pragma unroll 4
        for (int n = 0; n < 64; n++) s += tile[n * 129 + tid];
        g_SVp[(size_t)nt * 256 + v0 + tid] = s;
    }
}

// ---------------- phi (fused Q+K): 64-tok x 256-feat tile, K in 2x64 chunks ----------------
#define PHI_A_HI  2048
#define PHI_A_LO  (PHI_A_HI + 9216)
#define PHI_B_HI  (PHI_A_LO + 9216)
#define PHI_B_LO  (PHI_B_HI + 36864)
#define PHI_SMEM  (PHI_B_LO + 36864)    /* 94208 */

__global__ __launch_bounds__(256, 2)
void phi_kernel(const float* __restrict__ Q, const float* __restrict__ K)
{
    extern __shared__ char smem[];
    const uint32_t sb = smem_u32(smem);
    const int tid = threadIdx.x, wid = tid >> 5, lane = tid & 31;
    const bool isq = blockIdx.x < 512;
    const int tile = blockIdx.x & 511;
    const int row0 = tile * 64;
    const float* X = isq ? Q : K;
    const int m0 = (wid & 1) * 32, n0 = (wid >> 1) * 64, warpN = wid >> 1;

    float* h_sm    = (float*)smem;               // [64]
    float* rmax_sm = (float*)(smem + 256);       // [64]
    float* rmaxp   = (float*)(smem + 512);       // [64][4]
    float* wm_sm   = (float*)(smem + 1536);      // [2]
    float* bmax_s  = (float*)(smem + 1568);      // [1]
    float* w_sm    = (float*)(smem + 1600);      // [64]
    float* dbuf    = (float*)(smem + PHI_A_HI);  // [64][257]

    float c[2][8][4];
#pragma unroll
    for (int mt = 0; mt < 2; mt++)
#pragma unroll
        for (int nt = 0; nt < 8; nt++)
#pragma unroll
            for (int q = 0; q < 4; q++) c[mt][nt][q] = 0.f;

    const int arow = tid >> 2, aq = tid & 3;
#pragma unroll
    for (int ck = 0; ck < 2; ck++) {
        stage_async<256>(sb + PHI_B_HI, g_omTH + ck * 64, DQK, tid);
        stage_async<256>(sb + PHI_B_LO, g_omTL + ck * 64, DQK, tid);
        CP_COMMIT();
        const float4* xr = (const float4*)(X + (size_t)(row0 + arow) * DQK + ck * 64 + aq * 16);
        float hp = 0.f;
#pragma unroll
        for (int j = 0; j < 4; j++) {
            float4 v = xr[j];
            v.x *= INV_D4; v.y *= INV_D4; v.z *= INV_D4; v.w *= INV_D4;
            hp += v.x * v.x + v.y * v.y + v.z * v.z + v.w * v.w;
            uint32_t hwA, lwA, hwB, lwB;
            split_pair(v.x, v.y, hwA, lwA);
            split_pair(v.z, v.w, hwB, lwB);
            uint32_t off = (uint32_t)(arow * SP + aq * 16 + j * 4) * 2u;
            *(uint2*)(smem + PHI_A_HI + off) = make_uint2(hwA, hwB);
            *(uint2*)(smem + PHI_A_LO + off) = make_uint2(lwA, lwB);
        }
        hp += __shfl_xor_sync(0xffffffffu, hp, 1);
        hp += __shfl_xor_sync(0xffffffffu, hp, 2);
        if ((lane & 3) == 0) {
            if (ck == 0) h_sm[arow] = 0.5f * hp;
            else         h_sm[arow] += 0.5f * hp;
        }
        CP_WAIT0();
        __syncthreads();
        gemm_chunk<4, SP>(c, sb + PHI_A_HI, sb + PHI_A_LO, sb + PHI_B_HI, sb + PHI_B_LO,
                          lane, m0, n0);
        __syncthreads();
    }

    float rmx[2][2] = {{-3.0e38f, -3.0e38f}, {-3.0e38f, -3.0e38f}};
#pragma unroll
    for (int mt = 0; mt < 2; mt++)
#pragma unroll
        for (int nt = 0; nt < 8; nt++) {
            rmx[mt][0] = fmaxf(rmx[mt][0], fmaxf(c[mt][nt][0], c[mt][nt][1]));
            rmx[mt][1] = fmaxf(rmx[mt][1], fmaxf(c[mt][nt][2], c[mt][nt][3]));
        }
#pragma unroll
    for (int mt = 0; mt < 2; mt++)
#pragma unroll
        for (int hh = 0; hh < 2; hh++) {
            float v = rmx[mt][hh];
            v = fmaxf(v, __shfl_xor_sync(0xffffffffu, v, 1));
            v = fmaxf(v, __shfl_xor_sync(0xffffffffu, v, 2));
            rmx[mt][hh] = v;
        }
    {
        int g = lane >> 2;
        if ((lane & 3) == 0) {
            rmaxp[(m0 + g) * 4 + warpN]      = rmx[0][0];
            rmaxp[(m0 + g + 8) * 4 + warpN]  = rmx[0][1];
            rmaxp[(m0 + 16 + g) * 4 + warpN] = rmx[1][0];
            rmaxp[(m0 + 24 + g) * 4 + warpN] = rmx[1][1];
        }
    }
    __syncthreads();
    if (tid < 64) {
        float rm = fmaxf(fmaxf(rmaxp[tid * 4], rmaxp[tid * 4 + 1]),
                         fmaxf(rmaxp[tid * 4 + 2], rmaxp[tid * 4 + 3]));
        rmax_sm[tid] = rm;
        if (!isq) {
            g_rowmax[row0 + tid] = rm;
            float bm = warpMax(rm);
            if (lane == 0) wm_sm[wid] = bm;
        }
    }
    __syncthreads();
    if (!isq) {
        if (tid == 0) {
            float bm = fmaxf(wm_sm[0], wm_sm[1]);
            bmax_s[0] = bm;
            g_bmax[tile] = bm;
            atomicMax(&g_segmax[tile >> 3], f2o(bm));
        }
        __syncthreads();
        if (tid < 64) w_sm[tid] = __expf(rmax_sm[tid] - bmax_s[0]);
    }

    if (isq) {
        int g = lane >> 2, j = lane & 3;
#pragma unroll
        for (int mt = 0; mt < 2; mt++) {
            int r0 = m0 + mt * 16 + g, r1 = r0 + 8;
            float hm0 = h_sm[r0] + rmax_sm[r0];
            float hm1 = h_sm[r1] + rmax_sm[r1];
#pragma unroll
            for (int nt = 0; nt < 8; nt++) {
                int col = n0 + nt * 8 + j * 2;
                float v0 = (__expf(c[mt][nt][0] - hm0) + EPS_PHI) * INV_SQRT_M;
                float v1 = (__expf(c[mt][nt][1] - hm0) + EPS_PHI) * INV_SQRT_M;
                float v2 = (__expf(c[mt][nt][2] - hm1) + EPS_PHI) * INV_SQRT_M;
                float v3 = (__expf(c[mt][nt][3] - hm1) + EPS_PHI) * INV_SQRT_M;
                uint32_t hw, lw;
                split_pair(v0, v1, hw, lw);
                *(uint32_t*)&g_QpH[(size_t)(row0 + r0) * MF + col] = hw;
                *(uint32_t*)&g_QpL[(size_t)(row0 + r0) * MF + col] = lw;
                split_pair(v2, v3, hw, lw);
                *(uint32_t*)&g_QpH[(size_t)(row0 + r1) * MF + col] = hw;
                *(uint32_t*)&g_QpL[(size_t)(row0 + r1) * MF + col] = lw;
            }
        }
    } else {
        int g = lane >> 2;
        float e[2][8][4];
#pragma unroll
        for (int mt = 0; mt < 2; mt++) {
            int r0 = m0 + mt * 16 + g, r1 = r0 + 8;
            float hm0 = h_sm[r0] + rmax_sm[r0];
            float hm1 = h_sm[r1] + rmax_sm[r1];
#pragma unroll
            for (int nt = 0; nt < 8; nt++) {
                e[mt][nt][0] = __expf(c[mt][nt][0] - hm0);
                e[mt][nt][1] = __expf(c[mt][nt][1] - hm0);
                e[mt][nt][2] = __expf(c[mt][nt][2] - hm1);
                e[mt][nt][3] = __expf(c[mt][nt][3] - hm1);
            }
        }
        __syncthreads();
        frag_to_dbuf<257>(dbuf, e, lane, m0, n0);
        __syncthreads();
#pragma unroll 4
        for (int i = 0; i < 32; i++) {
            int f = i * 256 + tid, feat = f >> 5, tp = (f & 31) * 2;
            uint32_t hw, lw;
            split_pair(dbuf[tp * 257 + feat], dbuf[(tp + 1) * 257 + feat], hw, lw);
            *(uint32_t*)&g_KpTH[(size_t)feat * N_TOK + row0 + tp] = hw;
            *(uint32_t*)&g_KpTL[(size_t)feat * N_TOK + row0 + tp] = lw;
        }
        float s = 0.f;
#pragma unroll 4
        for (int t = 0; t < 64; t++) s += dbuf[t * 257 + tid] * w_sm[t];
        g_W[tile * 256 + tid] = s;
    }
}

// ---------------- kv: pipelined 32-wide chunks, 2-deep ----------------
#define P_AH  0
#define P_AL  10240
#define P_BH  20480
#define P_BL  30720
#define P_SZ  40960
#define KV_SV   81920
#define KV_SMEM (KV_SV + 512)

__global__ __launch_bounds__(256, 2)
void kv_kernel()
{
    extern __shared__ char smem[];
    const uint32_t sb = smem_u32(smem);
    const int tid = threadIdx.x, wid = tid >> 5, lane = tid & 31;
    const int b = blockIdx.x >> 2, mt_ = (blockIdx.x >> 1) & 1, vt = blockIdx.x & 1;
    const int m0g = mt_ * 128, v0 = vt * 128;
    const int m0 = (wid & 3) * 32, n0 = (wid >> 2) * 64;
    const size_t nb = (size_t)b * NPER;
    const uint16_t* AHg = g_KpTH + (size_t)m0g * N_TOK;
    const uint16_t* ALg = g_KpTL + (size_t)m0g * N_TOK;
    const uint16_t* BHg = g_VTH + (size_t)v0 * N_TOK;
    const uint16_t* BLg = g_VTL + (size_t)v0 * N_TOK;

    float c[2][8][4];
#pragma unroll
    for (int mt = 0; mt < 2; mt++)
#pragma unroll
        for (int nt = 0; nt < 8; nt++)
#pragma unroll
            for (int q = 0; q < 4; q++) c[mt][nt][q] = 0.f;

    // prologue
    {
        stage32(sb + P_AH, AHg + nb, N_TOK, tid);
        stage32(sb + P_AL, ALg + nb, N_TOK, tid);
        stage32(sb + P_BH, BHg + nb, N_TOK, tid);
        stage32(sb + P_BL, BLg + nb, N_TOK, tid);
        CP_COMMIT();
    }
    for (int ch = 0; ch < 16; ch++) {
        if (ch < 15) {
            uint32_t s1 = sb + ((ch + 1) & 1) * P_SZ;
            size_t nc = nb + (ch + 1) * 32;
            stage32(s1 + P_AH, AHg + nc, N_TOK, tid);
            stage32(s1 + P_AL, ALg + nc, N_TOK, tid);
            stage32(s1 + P_BH, BHg + nc, N_TOK, tid);
            stage32(s1 + P_BL, BLg + nc, N_TOK, tid);
            CP_COMMIT();
            CP_WAIT1();
        } else {
            CP_WAIT0();
        }
        __syncthreads();
        uint32_t s0 = sb + (ch & 1) * P_SZ;
        gemm_chunk<2, SP32>(c, s0 + P_AH, s0 + P_AL, s0 + P_BH, s0 + P_BL, lane, m0, n0);
        __syncthreads();
    }

    float* dbuf = (float*)smem;                    // [128][129]
    float* sv   = (float*)(smem + KV_SV);          // [128]
    frag_to_dbuf<129>(dbuf, c, lane, m0, n0);
    if (tid < 128) {
        const float* P = g_SVp + (size_t)(8 * b) * 256 + v0 + tid;
        float s = 0.f;
#pragma unroll
        for (int t = 0; t < 8; t++) s += P[t * 256];
        sv[tid] = s * EPS_PHI;
    }
    __syncthreads();
#pragma unroll 4
    for (int i = 0; i < 32; i++) {
        int f = i * 256 + tid, v = f >> 6, mp = (f & 63) * 2;
        float base = sv[v];
        float v0f = (dbuf[mp * 129 + v] + base) * INV_SQRT_M;
        float v1f = (dbuf[(mp + 1) * 129 + v] + base) * INV_SQRT_M;
        uint32_t hw, lw;
        split_pair(v0f, v1f, hw, lw);
        *(uint32_t*)&g_KVTH[((size_t)b * DV + v0 + v) * MF + m0g + mp] = hw;
        *(uint32_t*)&g_KVTL[((size_t)b * DV + v0 + v) * MF + m0g + mp] = lw;
    }
}

// ---------------- out: pipelined 32-wide chunks, norm fused ----------------
#define OUT_KSUM  81920
#define OUT_WT    (OUT_KSUM + 1024)
#define OUT_NRM   (OUT_WT + 64)
#define OUT_SMEM  (OUT_NRM + 512)

__global__ __launch_bounds__(256, 2)
void out_kernel(float* __restrict__ Out)
{
    extern __shared__ char smem[];
    const uint32_t sb = smem_u32(smem);
    const int tid = threadIdx.x, wid = tid >> 5, lane = tid & 31;
    const int b = blockIdx.x >> 3, rt = (blockIdx.x >> 1) & 3, vt = blockIdx.x & 1;
    const int row0 = b * NPER + rt * 128, v0 = vt * 128;
    const int m0 = (wid & 3) * 32, n0 = (wid >> 2) * 64;
    float* ksum = (float*)(smem + OUT_KSUM);       // [256]
    float* wtp  = (float*)(smem + OUT_WT);         // [8]
    const uint16_t* AHg = g_QpH + (size_t)row0 * MF;
    const uint16_t* ALg = g_QpL + (size_t)row0 * MF;
    const uint16_t* BHg = g_KVTH + ((size_t)b * DV + v0) * MF;
    const uint16_t* BLg = g_KVTL + ((size_t)b * DV + v0) * MF;

    if (tid < 8) wtp[tid] = __expf(g_bmax[b * 8 + tid] - o2f(g_segmax[b]));
    __syncthreads();
    {
        float s = 0.f;
#pragma unroll
        for (int t = 0; t < 8; t++) s += g_W[(size_t)(8 * b + t) * 256 + tid] * wtp[t];
        ksum[tid] = (s + 512.0f * EPS_PHI) * INV_SQRT_M;
    }

    float c[2][8][4];
#pragma unroll
    for (int mt = 0; mt < 2; mt++)
#pragma unroll
        for (int nt = 0; nt < 8; nt++)
#pragma unroll
            for (int q = 0; q < 4; q++) c[mt][nt][q] = 0.f;

    const int qrow = tid >> 1, qoff = (tid & 1) * 16;
    float qd = 0.f;

    {
        stage32(sb + P_AH, AHg, MF, tid);
        stage32(sb + P_AL, ALg, MF, tid);
        stage32(sb + P_BH, BHg, MF, tid);
        stage32(sb + P_BL, BLg, MF, tid);
        CP_COMMIT();
    }
    for (int ch = 0; ch < 8; ch++) {
        if (ch < 7) {
            uint32_t s1 = sb + ((ch + 1) & 1) * P_SZ;
            int k0 = (ch + 1) * 32;
            stage32(s1 + P_AH, AHg + k0, MF, tid);
            stage32(s1 + P_AL, ALg + k0, MF, tid);
            stage32(s1 + P_BH, BHg + k0, MF, tid);
            stage32(s1 + P_BL, BLg + k0, MF, tid);
            CP_COMMIT();
            CP_WAIT1();
        } else {
            CP_WAIT0();
        }
        __syncthreads();
        uint32_t s0 = sb + (ch & 1) * P_SZ;
        // qdot partial from staged A (Qp hi+lo) against ksum
        {
            const uint16_t* AH = (const uint16_t*)(smem + (ch & 1) * P_SZ + P_AH);
            const uint16_t* AL = (const uint16_t*)(smem + (ch & 1) * P_SZ + P_AL);
            int k0 = ch * 32;
            float qp = 0.f;
#pragma unroll
            for (int jq = 0; jq < 4; jq++) {
                uint2 h2 = *(const uint2*)&AH[qrow * SP32 + qoff + jq * 4];
                uint2 l2 = *(const uint2*)&AL[qrow * SP32 + qoff + jq * 4];
                const uint16_t* hp = (const uint16_t*)&h2;
                const uint16_t* lp = (const uint16_t*)&l2;
#pragma unroll
                for (int j = 0; j < 4; j++)
                    qp += from2(hp[j], lp[j]) * ksum[k0 + qoff + jq * 4 + j];
            }
            qd += qp;
        }
        gemm_chunk<2, SP32>(c, s0 + P_AH, s0 + P_AL, s0 + P_BH, s0 + P_BL, lane, m0, n0);
        __syncthreads();
    }

    qd += __shfl_xor_sync(0xffffffffu, qd, 1);

    float* dbuf   = (float*)smem;                  // [128][129]
    float* nrm_sm = (float*)(smem + OUT_NRM);      // [128]
    frag_to_dbuf<129>(dbuf, c, lane, m0, n0);
    if ((tid & 1) == 0) nrm_sm[qrow] = 1.0f / (qd + EPS_NORM);
    __syncthreads();
#pragma unroll
    for (int i = 0; i < 16; i++) {
        int f = i * 256 + tid, rr = f >> 5, c4 = (f & 31) * 4;
        float inv = nrm_sm[rr];
        float4 o = make_float4(dbuf[rr * 129 + c4] * inv, dbuf[rr * 129 + c4 + 1] * inv,
                               dbuf[rr * 129 + c4 + 2] * inv, dbuf[rr * 129 + c4 + 3] * inv);
        *(float4*)(Out + (size_t)(row0 + rr) * DV + v0 + c4) = o;
    }
}

// ---------------- launch ----------------
extern "C" void kernel_launch(void* const* d_in, const int* in_sizes, int n_in,
                              void* d_out, int out_size)
{
    (void)in_sizes; (void)n_in; (void)out_size;
    const float* Q     = (const float*)d_in[0];
    const float* K     = (const float*)d_in[1];
    const float* V     = (const float*)d_in[2];
    const float* omega = (const float*)d_in[3];
    float* Out = (float*)d_out;

    cudaFuncSetAttribute(omT_kernel,  cudaFuncAttributeMaxDynamicSharedMemorySize, OMT_SMEM);
    cudaFuncSetAttribute(vT_kernel,   cudaFuncAttributeMaxDynamicSharedMemorySize, VT_SMEM);
    cudaFuncSetAttribute(phi_kernel,  cudaFuncAttributeMaxDynamicSharedMemorySize, PHI_SMEM);
    cudaFuncSetAttribute(kv_kernel,   cudaFuncAttributeMaxDynamicSharedMemorySize, KV_SMEM);
    cudaFuncSetAttribute(out_kernel,  cudaFuncAttributeMaxDynamicSharedMemorySize, OUT_SMEM);

    omT_kernel<<<4, 256, OMT_SMEM>>>(omega);
    phi_kernel<<<1024, 256, PHI_SMEM>>>(Q, K);
    vT_kernel<<<dim3(512, 2), 256, VT_SMEM>>>(V);
    kv_kernel<<<256, 256, KV_SMEM>>>();
    out_kernel<<<512, 256, OUT_SMEM>>>(Out);
}

// round 10
// speedup vs baseline: 1.0480x; 1.0480x over previous
#include <cuda_runtime.h>
#include <cuda_bf16.h>
#include <cstdint>

#define N_TOK   32768
#define NBATCH  64
#define NPER    512
#define DQK     128
#define MF      256
#define DV      256
#define SP      72    /* bf16 row stride, 64-col tiles */

#define INV_D4      0.29730177875068026f
#define INV_SQRT_M  0.0625f
#define EPS_PHI     1e-4f
#define EPS_NORM    1e-8f

// ---------------- scratch ----------------
__device__ uint16_t g_QpH [(size_t)N_TOK * MF], g_QpL [(size_t)N_TOK * MF];   // [tok][feat]
__device__ uint16_t g_KpTH[(size_t)MF * N_TOK], g_KpTL[(size_t)MF * N_TOK];   // Kp0^T [feat][tok]
__device__ uint16_t g_VTH [(size_t)DV * N_TOK], g_VTL [(size_t)DV * N_TOK];   // (s*V)^T [v][tok]
__device__ uint16_t g_omTH[(size_t)MF * DQK],   g_omTL[(size_t)MF * DQK];
__device__ uint16_t g_KVTH[(size_t)NBATCH * DV * MF], g_KVTL[(size_t)NBATCH * DV * MF];
__device__ float    g_rowmax[N_TOK];
__device__ float    g_bmax[512];                 // per 64-token tile
__device__ unsigned g_segmax[NBATCH];
__device__ float    g_W  [512 * MF];             // weighted Kp0 colsum per 64-tok tile
__device__ float    g_SVp[(size_t)512 * DV];     // unweighted V colsum per 64-tok tile

// ---------------- helpers ----------------
__device__ __forceinline__ uint32_t smem_u32(const void* p) {
    uint32_t a;
    asm("{ .reg .u64 t; cvta.to.shared.u64 t, %1; cvt.u32.u64 %0, t; }" : "=r"(a) : "l"(p));
    return a;
}
__device__ __forceinline__ void ldsm4(uint32_t* r, uint32_t a) {
    asm volatile("ldmatrix.sync.aligned.m8n8.x4.shared.b16 {%0,%1,%2,%3}, [%4];"
        : "=r"(r[0]), "=r"(r[1]), "=r"(r[2]), "=r"(r[3]) : "r"(a));
}
__device__ __forceinline__ void mma16816(float* c, const uint32_t* a, const uint32_t* b) {
    asm volatile("mma.sync.aligned.m16n8k16.row.col.f32.bf16.bf16.f32 "
        "{%0,%1,%2,%3}, {%4,%5,%6,%7}, {%8,%9}, {%0,%1,%2,%3};"
        : "+f"(c[0]), "+f"(c[1]), "+f"(c[2]), "+f"(c[3])
        : "r"(a[0]), "r"(a[1]), "r"(a[2]), "r"(a[3]), "r"(b[0]), "r"(b[1]));
}
__device__ __forceinline__ void split1(float v, uint16_t& h, uint16_t& l) {
    __nv_bfloat16 hh = __float2bfloat16(v);
    __nv_bfloat16 ll = __float2bfloat16(v - __bfloat162float(hh));
    h = __bfloat16_as_ushort(hh); l = __bfloat16_as_ushort(ll);
}
__device__ __forceinline__ void split_pair(float a, float b, uint32_t& hw, uint32_t& lw) {
    uint16_t h0, l0, h1, l1;
    split1(a, h0, l0); split1(b, h1, l1);
    hw = (uint32_t)h0 | ((uint32_t)h1 << 16);
    lw = (uint32_t)l0 | ((uint32_t)l1 << 16);
}
__device__ __forceinline__ float from2(uint16_t h, uint16_t l) {
    return __bfloat162float(__ushort_as_bfloat16(h)) + __bfloat162float(__ushort_as_bfloat16(l));
}
__device__ __forceinline__ unsigned f2o(float f) {
    unsigned u = __float_as_uint(f);
    return (u & 0x80000000u) ? ~u : (u | 0x80000000u);
}
__device__ __forceinline__ float o2f(unsigned u) {
    return (u & 0x80000000u) ? __uint_as_float(u & 0x7fffffffu) : __uint_as_float(~u);
}
__device__ __forceinline__ float warpMax(float v) {
#pragma unroll
    for (int o = 16; o > 0; o >>= 1) v = fmaxf(v, __shfl_xor_sync(0xffffffffu, v, o));
    return v;
}
#define CP_COMMIT() asm volatile("cp.async.commit_group;" ::: "memory")
#define CP_WAIT0()  asm volatile("cp.async.wait_group 0;" ::: "memory")
#define CP_WAIT1()  asm volatile("cp.async.wait_group 1;" ::: "memory")

// stage ROWS x 64 u16 tile (stride SP) via cp.async, THREADS threads
template <int ROWS, int THREADS>
__device__ __forceinline__ void stage_async(uint32_t sdst, const uint16_t* __restrict__ g,
                                            size_t stride, int tid)
{
    constexpr int ITER = ROWS * 8 / THREADS;
#pragma unroll
    for (int i = 0; i < ITER; i++) {
        int idx = i * THREADS + tid;
        int r = idx >> 3, ck = idx & 7;
        uint32_t sa = sdst + (uint32_t)(r * SP * 2 + ck * 16);
        const void* ga = (const void*)(g + (size_t)r * stride + ck * 8);
        asm volatile("cp.async.cg.shared.global [%0], [%1], 16;" :: "r"(sa), "l"(ga));
    }
}

// ---------------- warp-tiled bf16x3 GEMM: one 64-wide K chunk, warp tile 32x64 ----------------
__device__ __forceinline__ void gemm_chunk(float c[2][8][4],
    uint32_t Ahi, uint32_t Alo, uint32_t Bhi, uint32_t Blo, int lane, int m0, int n0)
{
    const uint32_t ao0 = (uint32_t)((m0 + (lane & 15)) * SP + (lane >> 4) * 8) * 2u;
    const uint32_t bo0 = (uint32_t)((n0 + ((lane >> 4) << 3) + (lane & 7)) * SP
                                    + ((lane >> 3) & 1) * 8) * 2u;
#pragma unroll
    for (int ks = 0; ks < 4; ks++) {
        uint32_t ah[2][4], al[2][4];
        ldsm4(ah[0], Ahi + ao0 + ks * 32);
        ldsm4(ah[1], Ahi + ao0 + 16 * SP * 2 + ks * 32);
        ldsm4(al[0], Alo + ao0 + ks * 32);
        ldsm4(al[1], Alo + ao0 + 16 * SP * 2 + ks * 32);
#pragma unroll
        for (int n2 = 0; n2 < 4; n2++) {
            uint32_t bh[4], bl[4];
            ldsm4(bh, Bhi + bo0 + n2 * 16 * SP * 2 + ks * 32);
            ldsm4(bl, Blo + bo0 + n2 * 16 * SP * 2 + ks * 32);
#pragma unroll
            for (int mt = 0; mt < 2; mt++) {
                mma16816(c[mt][n2 * 2],     ah[mt], &bh[0]);
                mma16816(c[mt][n2 * 2],     al[mt], &bh[0]);
                mma16816(c[mt][n2 * 2],     ah[mt], &bl[0]);
                mma16816(c[mt][n2 * 2 + 1], ah[mt], &bh[2]);
                mma16816(c[mt][n2 * 2 + 1], al[mt], &bh[2]);
                mma16816(c[mt][n2 * 2 + 1], ah[mt], &bl[2]);
            }
        }
    }
}

// fragments -> f32 smem dbuf, row stride DS
template <int DS>
__device__ __forceinline__ void frag_to_dbuf(float* dbuf, const float c[2][8][4],
                                             int lane, int m0, int n0)
{
    int g = lane >> 2, j = lane & 3;
#pragma unroll
    for (int mt = 0; mt < 2; mt++)
#pragma unroll
        for (int nt = 0; nt < 8; nt++) {
            int r0 = m0 + mt * 16 + g, cc = n0 + nt * 8 + j * 2;
            dbuf[r0 * DS + cc]           = c[mt][nt][0];
            dbuf[r0 * DS + cc + 1]       = c[mt][nt][1];
            dbuf[(r0 + 8) * DS + cc]     = c[mt][nt][2];
            dbuf[(r0 + 8) * DS + cc + 1] = c[mt][nt][3];
        }
}

// ---------------- omega^T (4 CTAs) + segmax init ----------------
#define OMT_SMEM (128 * 65 * 4)
__global__ __launch_bounds__(256)
void omT_kernel(const float* __restrict__ omega) {
    extern __shared__ char smem[];
    float* tile = (float*)smem;                       // [128][65]
    const int tid = threadIdx.x;
    if (blockIdx.x == 0 && tid < NBATCH) g_segmax[tid] = 0u;
    const int m0 = blockIdx.x * 64;
#pragma unroll
    for (int i = 0; i < 32; i++) {
        int f = i * 256 + tid, k = f >> 6, mm = f & 63;
        tile[k * 65 + mm] = omega[k * MF + m0 + mm];
    }
    __syncthreads();
#pragma unroll
    for (int i = 0; i < 8; i++) {
        int f = i * 256 + tid, mm = f >> 5, kq = (f & 31) * 4;
        uint32_t h0, l0, h1, l1;
        split_pair(tile[kq * 65 + mm],       tile[(kq + 1) * 65 + mm], h0, l0);
        split_pair(tile[(kq + 2) * 65 + mm], tile[(kq + 3) * 65 + mm], h1, l1);
        *(uint2*)&g_omTH[(size_t)(m0 + mm) * DQK + kq] = make_uint2(h0, h1);
        *(uint2*)&g_omTL[(size_t)(m0 + mm) * DQK + kq] = make_uint2(l0, l1);
    }
}

// ---------------- vT: (s*V)^T planes + V colsum partials (64n x 128v tiles) ----------------
#define VT_SMEM (64 * 129 * 4 + 256)
__global__ __launch_bounds__(256)
void vT_kernel(const float* __restrict__ V) {
    extern __shared__ char smem[];
    float* tile = (float*)smem;                       // [64][129]
    float* s_sm = (float*)(smem + 64 * 129 * 4);      // [64]
    const int tid = threadIdx.x;
    const int nt = blockIdx.x, n0 = nt * 64, v0 = blockIdx.y * 128;
    if (tid < 64) s_sm[tid] = __expf(g_rowmax[n0 + tid] - o2f(g_segmax[n0 >> 9]));
#pragma unroll
    for (int i = 0; i < 32; i++) {
        int f = i * 256 + tid, n = f >> 7, v = f & 127;
        tile[n * 129 + v] = V[(size_t)(n0 + n) * DV + v0 + v];
    }
    __syncthreads();
#pragma unroll
    for (int i = 0; i < 8; i++) {
        int f = i * 256 + tid, v = f >> 4, nq = (f & 15) * 4;
        uint32_t h0, l0, h1, l1;
        split_pair(tile[nq * 129 + v] * s_sm[nq],
                   tile[(nq + 1) * 129 + v] * s_sm[nq + 1], h0, l0);
        split_pair(tile[(nq + 2) * 129 + v] * s_sm[nq + 2],
                   tile[(nq + 3) * 129 + v] * s_sm[nq + 3], h1, l1);
        *(uint2*)&g_VTH[(size_t)(v0 + v) * N_TOK + n0 + nq] = make_uint2(h0, h1);
        *(uint2*)&g_VTL[(size_t)(v0 + v) * N_TOK + n0 + nq] = make_uint2(l0, l1);
    }
    if (tid < 128) {
        float s = 0.f;
#pragma unroll 4
        for (int n = 0; n < 64; n++) s += tile[n * 129 + tid];
        g_SVp[(size_t)nt * 256 + v0 + tid] = s;
    }
}

// ---------------- phi (fused Q+K): 64-tok x 256-feat tile, K in 2x64 chunks ----------------
#define PHI_A_HI  2048
#define PHI_A_LO  (PHI_A_HI + 9216)
#define PHI_B_HI  (PHI_A_LO + 9216)
#define PHI_B_LO  (PHI_B_HI + 36864)
#define PHI_SMEM  (PHI_B_LO + 36864)    /* 94208 */

__global__ __launch_bounds__(256, 2)
void phi_kernel(const float* __restrict__ Q, const float* __restrict__ K)
{
    extern __shared__ char smem[];
    const uint32_t sb = smem_u32(smem);
    const int tid = threadIdx.x, wid = tid >> 5, lane = tid & 31;
    const bool isq = blockIdx.x < 512;
    const int tile = blockIdx.x & 511;
    const int row0 = tile * 64;
    const float* X = isq ? Q : K;
    const int m0 = (wid & 1) * 32, n0 = (wid >> 1) * 64, warpN = wid >> 1;

    float* h_sm    = (float*)smem;               // [64]
    float* rmax_sm = (float*)(smem + 256);       // [64]
    float* rmaxp   = (float*)(smem + 512);       // [64][4]
    float* wm_sm   = (float*)(smem + 1536);      // [2]
    float* bmax_s  = (float*)(smem + 1568);      // [1]
    float* w_sm    = (float*)(smem + 1600);      // [64]
    float* dbuf    = (float*)(smem + PHI_A_HI);  // [64][257]

    float c[2][8][4];
#pragma unroll
    for (int mt = 0; mt < 2; mt++)
#pragma unroll
        for (int nt = 0; nt < 8; nt++)
#pragma unroll
            for (int q = 0; q < 4; q++) c[mt][nt][q] = 0.f;

    const int arow = tid >> 2, aq = tid & 3;
#pragma unroll
    for (int ck = 0; ck < 2; ck++) {
        stage_async<256, 256>(sb + PHI_B_HI, g_omTH + ck * 64, DQK, tid);
        stage_async<256, 256>(sb + PHI_B_LO, g_omTL + ck * 64, DQK, tid);
        CP_COMMIT();
        const float4* xr = (const float4*)(X + (size_t)(row0 + arow) * DQK + ck * 64 + aq * 16);
        float hp = 0.f;
#pragma unroll
        for (int j = 0; j < 4; j++) {
            float4 v = xr[j];
            v.x *= INV_D4; v.y *= INV_D4; v.z *= INV_D4; v.w *= INV_D4;
            hp += v.x * v.x + v.y * v.y + v.z * v.z + v.w * v.w;
            uint32_t hwA, lwA, hwB, lwB;
            split_pair(v.x, v.y, hwA, lwA);
            split_pair(v.z, v.w, hwB, lwB);
            uint32_t off = (uint32_t)(arow * SP + aq * 16 + j * 4) * 2u;
            *(uint2*)(smem + PHI_A_HI + off) = make_uint2(hwA, hwB);
            *(uint2*)(smem + PHI_A_LO + off) = make_uint2(lwA, lwB);
        }
        hp += __shfl_xor_sync(0xffffffffu, hp, 1);
        hp += __shfl_xor_sync(0xffffffffu, hp, 2);
        if ((lane & 3) == 0) {
            if (ck == 0) h_sm[arow] = 0.5f * hp;
            else         h_sm[arow] += 0.5f * hp;
        }
        CP_WAIT0();
        __syncthreads();
        gemm_chunk(c, sb + PHI_A_HI, sb + PHI_A_LO, sb + PHI_B_HI, sb + PHI_B_LO,
                   lane, m0, n0);
        __syncthreads();
    }

    float rmx[2][2] = {{-3.0e38f, -3.0e38f}, {-3.0e38f, -3.0e38f}};
#pragma unroll
    for (int mt = 0; mt < 2; mt++)
#pragma unroll
        for (int nt = 0; nt < 8; nt++) {
            rmx[mt][0] = fmaxf(rmx[mt][0], fmaxf(c[mt][nt][0], c[mt][nt][1]));
            rmx[mt][1] = fmaxf(rmx[mt][1], fmaxf(c[mt][nt][2], c[mt][nt][3]));
        }
#pragma unroll
    for (int mt = 0; mt < 2; mt++)
#pragma unroll
        for (int hh = 0; hh < 2; hh++) {
            float v = rmx[mt][hh];
            v = fmaxf(v, __shfl_xor_sync(0xffffffffu, v, 1));
            v = fmaxf(v, __shfl_xor_sync(0xffffffffu, v, 2));
            rmx[mt][hh] = v;
        }
    {
        int g = lane >> 2;
        if ((lane & 3) == 0) {
            rmaxp[(m0 + g) * 4 + warpN]      = rmx[0][0];
            rmaxp[(m0 + g + 8) * 4 + warpN]  = rmx[0][1];
            rmaxp[(m0 + 16 + g) * 4 + warpN] = rmx[1][0];
            rmaxp[(m0 + 24 + g) * 4 + warpN] = rmx[1][1];
        }
    }
    __syncthreads();
    if (tid < 64) {
        float rm = fmaxf(fmaxf(rmaxp[tid * 4], rmaxp[tid * 4 + 1]),
                         fmaxf(rmaxp[tid * 4 + 2], rmaxp[tid * 4 + 3]));
        rmax_sm[tid] = rm;
        if (!isq) {
            g_rowmax[row0 + tid] = rm;
            float bm = warpMax(rm);
            if (lane == 0) wm_sm[wid] = bm;
        }
    }
    __syncthreads();
    if (!isq) {
        if (tid == 0) {
            float bm = fmaxf(wm_sm[0], wm_sm[1]);
            bmax_s[0] = bm;
            g_bmax[tile] = bm;
            atomicMax(&g_segmax[tile >> 3], f2o(bm));
        }
        __syncthreads();
        if (tid < 64) w_sm[tid] = __expf(rmax_sm[tid] - bmax_s[0]);
    }

    if (isq) {
        int g = lane >> 2, j = lane & 3;
#pragma unroll
        for (int mt = 0; mt < 2; mt++) {
            int r0 = m0 + mt * 16 + g, r1 = r0 + 8;
            float hm0 = h_sm[r0] + rmax_sm[r0];
            float hm1 = h_sm[r1] + rmax_sm[r1];
#pragma unroll
            for (int nt = 0; nt < 8; nt++) {
                int col = n0 + nt * 8 + j * 2;
                float v0 = (__expf(c[mt][nt][0] - hm0) + EPS_PHI) * INV_SQRT_M;
                float v1 = (__expf(c[mt][nt][1] - hm0) + EPS_PHI) * INV_SQRT_M;
                float v2 = (__expf(c[mt][nt][2] - hm1) + EPS_PHI) * INV_SQRT_M;
                float v3 = (__expf(c[mt][nt][3] - hm1) + EPS_PHI) * INV_SQRT_M;
                uint32_t hw, lw;
                split_pair(v0, v1, hw, lw);
                *(uint32_t*)&g_QpH[(size_t)(row0 + r0) * MF + col] = hw;
                *(uint32_t*)&g_QpL[(size_t)(row0 + r0) * MF + col] = lw;
                split_pair(v2, v3, hw, lw);
                *(uint32_t*)&g_QpH[(size_t)(row0 + r1) * MF + col] = hw;
                *(uint32_t*)&g_QpL[(size_t)(row0 + r1) * MF + col] = lw;
            }
        }
    } else {
        int g = lane >> 2;
        float e[2][8][4];
#pragma unroll
        for (int mt = 0; mt < 2; mt++) {
            int r0 = m0 + mt * 16 + g, r1 = r0 + 8;
            float hm0 = h_sm[r0] + rmax_sm[r0];
            float hm1 = h_sm[r1] + rmax_sm[r1];
#pragma unroll
            for (int nt = 0; nt < 8; nt++) {
                e[mt][nt][0] = __expf(c[mt][nt][0] - hm0);
                e[mt][nt][1] = __expf(c[mt][nt][1] - hm0);
                e[mt][nt][2] = __expf(c[mt][nt][2] - hm1);
                e[mt][nt][3] = __expf(c[mt][nt][3] - hm1);
            }
        }
        __syncthreads();
        frag_to_dbuf<257>(dbuf, e, lane, m0, n0);
        __syncthreads();
#pragma unroll 4
        for (int i = 0; i < 32; i++) {
            int f = i * 256 + tid, feat = f >> 5, tp = (f & 31) * 2;
            uint32_t hw, lw;
            split_pair(dbuf[tp * 257 + feat], dbuf[(tp + 1) * 257 + feat], hw, lw);
            *(uint32_t*)&g_KpTH[(size_t)feat * N_TOK + row0 + tp] = hw;
            *(uint32_t*)&g_KpTL[(size_t)feat * N_TOK + row0 + tp] = lw;
        }
        float s = 0.f;
#pragma unroll 4
        for (int t = 0; t < 64; t++) s += dbuf[t * 257 + tid] * w_sm[t];
        g_W[tile * 256 + tid] = s;
    }
}

// ---------------- kv: tile 256m x 128v, 512 thr, 1 CTA/SM, depth-2 pipeline ----------------
// stage layout (per stage): AH 36864 | AL 36864 | BH 18432 | BL 18432 = 110592
#define KV_AH   0
#define KV_AL   36864
#define KV_BH   73728
#define KV_BL   92160
#define KV_SSZ  110592
#define KV_SV   221184
#define KV_SMEM (KV_SV + 512)

__global__ __launch_bounds__(512, 1)
void kv_kernel()
{
    extern __shared__ char smem[];
    const uint32_t sb = smem_u32(smem);
    const int tid = threadIdx.x, wid = tid >> 5, lane = tid & 31;
    const int b = blockIdx.x >> 1, vt = blockIdx.x & 1;
    const int v0 = vt * 128;
    const int m0 = (wid & 7) * 32, n0 = (wid >> 3) * 64;
    const size_t nb = (size_t)b * NPER;
    const uint16_t* BHg = g_VTH + (size_t)v0 * N_TOK;
    const uint16_t* BLg = g_VTL + (size_t)v0 * N_TOK;

    float c[2][8][4];
#pragma unroll
    for (int mt = 0; mt < 2; mt++)
#pragma unroll
        for (int nt = 0; nt < 8; nt++)
#pragma unroll
            for (int q = 0; q < 4; q++) c[mt][nt][q] = 0.f;

    // prologue: stage chunk 0
    {
        stage_async<256, 512>(sb + KV_AH, g_KpTH + nb, N_TOK, tid);
        stage_async<256, 512>(sb + KV_AL, g_KpTL + nb, N_TOK, tid);
        stage_async<128, 512>(sb + KV_BH, BHg + nb, N_TOK, tid);
        stage_async<128, 512>(sb + KV_BL, BLg + nb, N_TOK, tid);
        CP_COMMIT();
    }
    for (int ch = 0; ch < 8; ch++) {
        if (ch < 7) {
            uint32_t s1 = sb + ((ch + 1) & 1) * KV_SSZ;
            size_t nc = nb + (ch + 1) * 64;
            stage_async<256, 512>(s1 + KV_AH, g_KpTH + nc, N_TOK, tid);
            stage_async<256, 512>(s1 + KV_AL, g_KpTL + nc, N_TOK, tid);
            stage_async<128, 512>(s1 + KV_BH, BHg + nc, N_TOK, tid);
            stage_async<128, 512>(s1 + KV_BL, BLg + nc, N_TOK, tid);
            CP_COMMIT();
            CP_WAIT1();
        } else {
            CP_WAIT0();
        }
        __syncthreads();
        uint32_t s0 = sb + (ch & 1) * KV_SSZ;
        gemm_chunk(c, s0 + KV_AH, s0 + KV_AL, s0 + KV_BH, s0 + KV_BL, lane, m0, n0);
        __syncthreads();
    }

    // epilogue: KVT[b][v0+v][m] = (D[m][v] + eps*SV[v]) / sqrt(m)
    float* dbuf = (float*)smem;                    // [256][129]
    float* sv   = (float*)(smem + KV_SV);          // [128]
    frag_to_dbuf<129>(dbuf, c, lane, m0, n0);
    if (tid < 128) {
        const float* P = g_SVp + (size_t)(8 * b) * 256 + v0 + tid;
        float s = 0.f;
#pragma unroll
        for (int t = 0; t < 8; t++) s += P[t * 256];
        sv[tid] = s * EPS_PHI;
    }
    __syncthreads();
#pragma unroll 4
    for (int i = 0; i < 32; i++) {
        int f = i * 512 + tid, v = f >> 7, mp = (f & 127) * 2;
        float base = sv[v];
        float v0f = (dbuf[mp * 129 + v] + base) * INV_SQRT_M;
        float v1f = (dbuf[(mp + 1) * 129 + v] + base) * INV_SQRT_M;
        uint32_t hw, lw;
        split_pair(v0f, v1f, hw, lw);
        *(uint32_t*)&g_KVTH[((size_t)b * DV + v0 + v) * MF + mp] = hw;
        *(uint32_t*)&g_KVTL[((size_t)b * DV + v0 + v) * MF + mp] = lw;
    }
}

// ---------------- out: tile 128row x 256v, 512 thr, 1 CTA/SM, depth-2 pipeline ----------------
// stage layout (per stage): AH 18432 | AL 18432 | BH 36864 | BL 36864 = 110592
#define OU_AH   0
#define OU_AL   18432
#define OU_BH   36864
#define OU_BL   73728
#define OU_SSZ  110592
#define OU_KSUM 221184
#define OU_WT   (OU_KSUM + 1024)
#define OU_NRM  (OU_WT + 64)
#define OU_SMEM (OU_NRM + 512)

__global__ __launch_bounds__(512, 1)
void out_kernel(float* __restrict__ Out)
{
    extern __shared__ char smem[];
    const uint32_t sb = smem_u32(smem);
    const int tid = threadIdx.x, wid = tid >> 5, lane = tid & 31;
    const int b = blockIdx.x >> 2, rt = blockIdx.x & 3;
    const int row0 = b * NPER + rt * 128;
    const int m0 = (wid & 3) * 32, n0 = (wid >> 2) * 64;
    float* ksum = (float*)(smem + OU_KSUM);        // [256]
    float* wtp  = (float*)(smem + OU_WT);          // [8]
    const uint16_t* AHg = g_QpH + (size_t)row0 * MF;
    const uint16_t* ALg = g_QpL + (size_t)row0 * MF;
    const uint16_t* BHg = g_KVTH + (size_t)b * DV * MF;
    const uint16_t* BLg = g_KVTL + (size_t)b * DV * MF;

    if (tid < 8) wtp[tid] = __expf(g_bmax[b * 8 + tid] - o2f(g_segmax[b]));
    __syncthreads();
    if (tid < 256) {
        float s = 0.f;
#pragma unroll
        for (int t = 0; t < 8; t++) s += g_W[(size_t)(8 * b + t) * 256 + tid] * wtp[t];
        ksum[tid] = (s + 512.0f * EPS_PHI) * INV_SQRT_M;
    }

    float c[2][8][4];
#pragma unroll
    for (int mt = 0; mt < 2; mt++)
#pragma unroll
        for (int nt = 0; nt < 8; nt++)
#pragma unroll
            for (int q = 0; q < 4; q++) c[mt][nt][q] = 0.f;

    const int qrow = tid >> 2, qoff = (tid & 3) * 16;
    float qd = 0.f;

    {
        stage_async<128, 512>(sb + OU_AH, AHg, MF, tid);
        stage_async<128, 512>(sb + OU_AL, ALg, MF, tid);
        stage_async<256, 512>(sb + OU_BH, BHg, MF, tid);
        stage_async<256, 512>(sb + OU_BL, BLg, MF, tid);
        CP_COMMIT();
    }
    for (int ch = 0; ch < 4; ch++) {
        if (ch < 3) {
            uint32_t s1 = sb + ((ch + 1) & 1) * OU_SSZ;
            int k0 = (ch + 1) * 64;
            stage_async<128, 512>(s1 + OU_AH, AHg + k0, MF, tid);
            stage_async<128, 512>(s1 + OU_AL, ALg + k0, MF, tid);
            stage_async<256, 512>(s1 + OU_BH, BHg + k0, MF, tid);
            stage_async<256, 512>(s1 + OU_BL, BLg + k0, MF, tid);
            CP_COMMIT();
            CP_WAIT1();
        } else {
            CP_WAIT0();
        }
        __syncthreads();
        // qdot partial from staged A (Qp hi+lo) against ksum
        {
            const uint16_t* AH = (const uint16_t*)(smem + (ch & 1) * OU_SSZ + OU_AH);
            const uint16_t* AL = (const uint16_t*)(smem + (ch & 1) * OU_SSZ + OU_AL);
            int k0 = ch * 64;
            float qp = 0.f;
#pragma unroll
            for (int jq = 0; jq < 4; jq++) {
                uint2 h2 = *(const uint2*)&AH[qrow * SP + qoff + jq * 4];
                uint2 l2 = *(const uint2*)&AL[qrow * SP + qoff + jq * 4];
                const uint16_t* hp = (const uint16_t*)&h2;
                const uint16_t* lp = (const uint16_t*)&l2;
#pragma unroll
                for (int j = 0; j < 4; j++)
                    qp += from2(hp[j], lp[j]) * ksum[k0 + qoff + jq * 4 + j];
            }
            qd += qp;
        }
        uint32_t s0 = sb + (ch & 1) * OU_SSZ;
        gemm_chunk(c, s0 + OU_AH, s0 + OU_AL, s0 + OU_BH, s0 + OU_BL, lane, m0, n0);
        __syncthreads();
    }

    qd += __shfl_xor_sync(0xffffffffu, qd, 1);
    qd += __shfl_xor_sync(0xffffffffu, qd, 2);

    float* dbuf   = (float*)smem;                  // [128][257]
    float* nrm_sm = (float*)(smem + OU_NRM);       // [128]
    frag_to_dbuf<257>(dbuf, c, lane, m0, n0);
    if ((tid & 3) == 0) nrm_sm[qrow] = 1.0f / (qd + EPS_NORM);
    __syncthreads();
#pragma unroll
    for (int i = 0; i < 16; i++) {
        int f = i * 512 + tid, rr = f >> 6, c4 = (f & 63) * 4;
        float inv = nrm_sm[rr];
        float4 o = make_float4(dbuf[rr * 257 + c4] * inv, dbuf[rr * 257 + c4 + 1] * inv,
                               dbuf[rr * 257 + c4 + 2] * inv, dbuf[rr * 257 + c4 + 3] * inv);
        *(float4*)(Out + (size_t)(row0 + rr) * DV + c4) = o;
    }
}

// ---------------- launch ----------------
extern "C" void kernel_launch(void* const* d_in, const int* in_sizes, int n_in,
                              void* d_out, int out_size)
{
    (void)in_sizes; (void)n_in; (void)out_size;
    const float* Q     = (const float*)d_in[0];
    const float* K     = (const float*)d_in[1];
    const float* V     = (const float*)d_in[2];
    const float* omega = (const float*)d_in[3];
    float* Out = (float*)d_out;

    cudaFuncSetAttribute(omT_kernel,  cudaFuncAttributeMaxDynamicSharedMemorySize, OMT_SMEM);
    cudaFuncSetAttribute(vT_kernel,   cudaFuncAttributeMaxDynamicSharedMemorySize, VT_SMEM);
    cudaFuncSetAttribute(phi_kernel,  cudaFuncAttributeMaxDynamicSharedMemorySize, PHI_SMEM);
    cudaFuncSetAttribute(kv_kernel,   cudaFuncAttributeMaxDynamicSharedMemorySize, KV_SMEM);
    cudaFuncSetAttribute(out_kernel,  cudaFuncAttributeMaxDynamicSharedMemorySize, OU_SMEM);

    omT_kernel<<<4, 256, OMT_SMEM>>>(omega);
    phi_kernel<<<1024, 256, PHI_SMEM>>>(Q, K);
    vT_kernel<<<dim3(512, 2), 256, VT_SMEM>>>(V);
    kv_kernel<<<128, 512, KV_SMEM>>>();
    out_kernel<<<256, 512, OU_SMEM>>>(Out);
}

// round 11
// speedup vs baseline: 1.1398x; 1.0876x over previous
#include <cuda_runtime.h>
#include <cuda_bf16.h>
#include <cstdint>

#define N_TOK   32768
#define NBATCH  64
#define NPER    512
#define DQK     128
#define MF      256
#define DV      256
#define TS      4096   /* u16 per 64x64 tile */
#define TSB     8192   /* bytes per tile */

#define INV_D4      0.29730177875068026f
#define INV_SQRT_M  0.0625f
#define EPS_PHI     1e-4f
#define EPS_NORM    1e-8f

// ---------------- scratch (all operand arrays are pre-swizzled 64x64 u16 tiles) ----------------
__device__ uint16_t g_QpH [(size_t)N_TOK * MF], g_QpL [(size_t)N_TOK * MF];   // tiles [rt512][kt4]
__device__ uint16_t g_KpTH[(size_t)MF * N_TOK], g_KpTL[(size_t)MF * N_TOK];   // tiles [tt512][ft4]
__device__ uint16_t g_VTH [(size_t)DV * N_TOK], g_VTL [(size_t)DV * N_TOK];   // tiles [tt512][vt4]
__device__ uint16_t g_omTH[(size_t)MF * DQK],   g_omTL[(size_t)MF * DQK];     // tiles [kt2][mt4]
__device__ uint16_t g_KVTH[(size_t)NBATCH * DV * MF], g_KVTL[(size_t)NBATCH * DV * MF]; // [b][kt4][vt4]
__device__ float    g_rowmax[N_TOK];
__device__ float    g_bmax[512];
__device__ unsigned g_segmax[NBATCH];
__device__ float    g_W  [512 * MF];
__device__ float    g_SVp[(size_t)512 * DV];

// ---------------- helpers ----------------
__device__ __forceinline__ uint32_t smem_u32(const void* p) {
    uint32_t a;
    asm("{ .reg .u64 t; cvta.to.shared.u64 t, %1; cvt.u32.u64 %0, t; }" : "=r"(a) : "l"(p));
    return a;
}
__device__ __forceinline__ uint32_t swz(uint32_t off) { return off ^ ((off >> 3) & 0x70u); }
__device__ __forceinline__ void ldsm4(uint32_t* r, uint32_t a) {
    asm volatile("ldmatrix.sync.aligned.m8n8.x4.shared.b16 {%0,%1,%2,%3}, [%4];"
        : "=r"(r[0]), "=r"(r[1]), "=r"(r[2]), "=r"(r[3]) : "r"(a));
}
__device__ __forceinline__ void mma16816(float* c, const uint32_t* a, const uint32_t* b) {
    asm volatile("mma.sync.aligned.m16n8k16.row.col.f32.bf16.bf16.f32 "
        "{%0,%1,%2,%3}, {%4,%5,%6,%7}, {%8,%9}, {%0,%1,%2,%3};"
        : "+f"(c[0]), "+f"(c[1]), "+f"(c[2]), "+f"(c[3])
        : "r"(a[0]), "r"(a[1]), "r"(a[2]), "r"(a[3]), "r"(b[0]), "r"(b[1]));
}
__device__ __forceinline__ void split1(float v, uint16_t& h, uint16_t& l) {
    __nv_bfloat16 hh = __float2bfloat16(v);
    __nv_bfloat16 ll = __float2bfloat16(v - __bfloat162float(hh));
    h = __bfloat16_as_ushort(hh); l = __bfloat16_as_ushort(ll);
}
__device__ __forceinline__ void split_pair(float a, float b, uint32_t& hw, uint32_t& lw) {
    uint16_t h0, l0, h1, l1;
    split1(a, h0, l0); split1(b, h1, l1);
    hw = (uint32_t)h0 | ((uint32_t)h1 << 16);
    lw = (uint32_t)l0 | ((uint32_t)l1 << 16);
}
__device__ __forceinline__ float from2(uint16_t h, uint16_t l) {
    return __bfloat162float(__ushort_as_bfloat16(h)) + __bfloat162float(__ushort_as_bfloat16(l));
}
__device__ __forceinline__ unsigned f2o(float f) {
    unsigned u = __float_as_uint(f);
    return (u & 0x80000000u) ? ~u : (u | 0x80000000u);
}
__device__ __forceinline__ float o2f(unsigned u) {
    return (u & 0x80000000u) ? __uint_as_float(u & 0x7fffffffu) : __uint_as_float(~u);
}
__device__ __forceinline__ float warpMax(float v) {
#pragma unroll
    for (int o = 16; o > 0; o >>= 1) v = fmaxf(v, __shfl_xor_sync(0xffffffffu, v, o));
    return v;
}

#define MBAR_INIT(mb, c)   asm volatile("mbarrier.init.shared.b64 [%0], %1;" :: "r"((uint32_t)(mb)), "r"((uint32_t)(c)) : "memory")
#define MBAR_EXPECT(mb, tx) asm volatile("mbarrier.arrive.expect_tx.shared.b64 _, [%0], %1;" :: "r"((uint32_t)(mb)), "r"((uint32_t)(tx)) : "memory")
#define BULK_G2S(dst, src, bytes, mb) \
    asm volatile("cp.async.bulk.shared::cta.global.mbarrier::complete_tx::bytes [%0], [%1], %2, [%3];" \
        :: "r"((uint32_t)(dst)), "l"(src), "r"((uint32_t)(bytes)), "r"((uint32_t)(mb)) : "memory")
#define MBAR_WAIT(mb, ph) do {                                                     \
    uint32_t _m = (uint32_t)(mb), _p = (uint32_t)(ph), _d;                         \
    asm volatile("{ .reg .pred p; mbarrier.try_wait.parity.acquire.cta.shared::cta.b64 p, [%1], %2;" \
                 " selp.b32 %0,1,0,p; }" : "=r"(_d) : "r"(_m), "r"(_p) : "memory");\
    if (!_d) {                                                                     \
        asm volatile("{ .reg .pred P1; W%=:"                                       \
            " mbarrier.try_wait.parity.acquire.cta.shared::cta.b64 P1, [%0], %1, 0x989680;" \
            " @P1 bra.uni D%=; bra.uni W%=; D%=: }" :: "r"(_m), "r"(_p) : "memory"); \
    } } while (0)

// ---------------- warp-tiled bf16x3 GEMM on swizzled 64x64 tiles: one 64-wide K chunk ----------------
// A region: tiles along m (row>>6); B region: tiles along n. C = Ah*Bh + Al*Bh + Ah*Bl.
__device__ __forceinline__ void gemm_chunk(float c[2][8][4],
    uint32_t Ahi, uint32_t Alo, uint32_t Bhi, uint32_t Blo, int lane, int m0, int n0)
{
    uint32_t at[2], arx[2];
#pragma unroll
    for (int mt = 0; mt < 2; mt++) {
        int row = m0 + mt * 16;
        int rl = (row & 63) + (lane & 15);
        at[mt]  = (uint32_t)(row >> 6) * TSB + (uint32_t)rl * 128u;
        arx[mt] = (uint32_t)(rl & 7) << 4;
    }
    const uint32_t acol = (uint32_t)((lane >> 4) * 16);
    uint32_t bt[4], brx[4];
#pragma unroll
    for (int n2 = 0; n2 < 4; n2++) {
        int row = n0 + n2 * 16;
        int rl = (row & 63) + (((lane >> 4) << 3) + (lane & 7));
        bt[n2]  = (uint32_t)(row >> 6) * TSB + (uint32_t)rl * 128u;
        brx[n2] = (uint32_t)(rl & 7) << 4;
    }
    const uint32_t bcol = (uint32_t)(((lane >> 3) & 1) * 16);
#pragma unroll
    for (int ks = 0; ks < 4; ks++) {
        uint32_t ah[2][4], al[2][4];
#pragma unroll
        for (int mt = 0; mt < 2; mt++) {
            uint32_t o = at[mt] + ((acol + ks * 32) ^ arx[mt]);
            ldsm4(ah[mt], Ahi + o);
            ldsm4(al[mt], Alo + o);
        }
#pragma unroll
        for (int n2 = 0; n2 < 4; n2++) {
            uint32_t bh[4], bl[4];
            uint32_t o = bt[n2] + ((bcol + ks * 32) ^ brx[n2]);
            ldsm4(bh, Bhi + o);
            ldsm4(bl, Blo + o);
#pragma unroll
            for (int mt = 0; mt < 2; mt++) {
                mma16816(c[mt][n2 * 2],     ah[mt], &bh[0]);
                mma16816(c[mt][n2 * 2],     al[mt], &bh[0]);
                mma16816(c[mt][n2 * 2],     ah[mt], &bl[0]);
                mma16816(c[mt][n2 * 2 + 1], ah[mt], &bh[2]);
                mma16816(c[mt][n2 * 2 + 1], al[mt], &bh[2]);
                mma16816(c[mt][n2 * 2 + 1], ah[mt], &bl[2]);
            }
        }
    }
}

// fragments -> f32 smem dbuf, row stride DS
template <int DS>
__device__ __forceinline__ void frag_to_dbuf(float* dbuf, const float c[2][8][4],
                                             int lane, int m0, int n0)
{
    int g = lane >> 2, j = lane & 3;
#pragma unroll
    for (int mt = 0; mt < 2; mt++)
#pragma unroll
        for (int nt = 0; nt < 8; nt++) {
            int r0 = m0 + mt * 16 + g, cc = n0 + nt * 8 + j * 2;
            dbuf[r0 * DS + cc]           = c[mt][nt][0];
            dbuf[r0 * DS + cc + 1]       = c[mt][nt][1];
            dbuf[(r0 + 8) * DS + cc]     = c[mt][nt][2];
            dbuf[(r0 + 8) * DS + cc + 1] = c[mt][nt][3];
        }
}

// ---------------- omega^T (4 CTAs, blockIdx = mt) + segmax init ----------------
#define OMT_SMEM (128 * 65 * 4)
__global__ __launch_bounds__(256)
void omT_kernel(const float* __restrict__ omega) {
    extern __shared__ char smem[];
    float* tile = (float*)smem;                       // [128 k][65 m]
    const int tid = threadIdx.x;
    if (blockIdx.x == 0 && tid < NBATCH) g_segmax[tid] = 0u;
    const int mt = blockIdx.x, m0 = mt * 64;
#pragma unroll
    for (int i = 0; i < 32; i++) {
        int f = i * 256 + tid, k = f >> 6, mm = f & 63;
        tile[k * 65 + mm] = omega[k * MF + m0 + mm];
    }
    __syncthreads();
#pragma unroll
    for (int i = 0; i < 8; i++) {
        int f = i * 256 + tid, mm = f >> 5, kq = (f & 31) * 4;
        uint32_t h0, l0, h1, l1;
        split_pair(tile[kq * 65 + mm],       tile[(kq + 1) * 65 + mm], h0, l0);
        split_pair(tile[(kq + 2) * 65 + mm], tile[(kq + 3) * 65 + mm], h1, l1);
        int kt = kq >> 6, kl = kq & 63;
        size_t base = ((size_t)kt * 4 + mt) * TS;
        uint32_t off = swz((uint32_t)(mm * 128 + kl * 2)) >> 1;
        *(uint2*)&g_omTH[base + off] = make_uint2(h0, h1);
        *(uint2*)&g_omTL[base + off] = make_uint2(l0, l1);
    }
}

// ---------------- vT: (s*V)^T swizzled tiles + V colsum partials ----------------
#define VT_SMEM (64 * 129 * 4 + 256)
__global__ __launch_bounds__(256)
void vT_kernel(const float* __restrict__ V) {
    extern __shared__ char smem[];
    float* tile = (float*)smem;                       // [64 n][129 v]
    float* s_sm = (float*)(smem + 64 * 129 * 4);      // [64]
    const int tid = threadIdx.x;
    const int nt = blockIdx.x, n0 = nt * 64, v0 = blockIdx.y * 128;
    if (tid < 64) s_sm[tid] = __expf(g_rowmax[n0 + tid] - o2f(g_segmax[n0 >> 9]));
#pragma unroll
    for (int i = 0; i < 32; i++) {
        int f = i * 256 + tid, n = f >> 7, v = f & 127;
        tile[n * 129 + v] = V[(size_t)(n0 + n) * DV + v0 + v];
    }
    __syncthreads();
#pragma unroll
    for (int i = 0; i < 8; i++) {
        int f = i * 256 + tid, v = f >> 4, nq = (f & 15) * 4;
        uint32_t h0, l0, h1, l1;
        split_pair(tile[nq * 129 + v] * s_sm[nq],
                   tile[(nq + 1) * 129 + v] * s_sm[nq + 1], h0, l0);
        split_pair(tile[(nq + 2) * 129 + v] * s_sm[nq + 2],
                   tile[(nq + 3) * 129 + v] * s_sm[nq + 3], h1, l1);
        int vt = (v0 >> 6) + (v >> 6), vr = v & 63;
        size_t base = ((size_t)nt * 4 + vt) * TS;
        uint32_t off = swz((uint32_t)(vr * 128 + nq * 2)) >> 1;
        *(uint2*)&g_VTH[base + off] = make_uint2(h0, h1);
        *(uint2*)&g_VTL[base + off] = make_uint2(l0, l1);
    }
    if (tid < 128) {
        float s = 0.f;
#pragma unroll 4
        for (int n = 0; n < 64; n++) s += tile[n * 129 + tid];
        g_SVp[(size_t)nt * 256 + v0 + tid] = s;
    }
}

// ---------------- phi (fused Q+K): 64-tok x 256-feat, K in 2x64 chunks, bulk-staged B ----------------
#define PHI_MBAR  1920
#define PHI_A_HI  2048
#define PHI_A_LO  (PHI_A_HI + TSB)
#define PHI_B_HI  (PHI_A_LO + TSB)
#define PHI_B_LO  (PHI_B_HI + 4 * TSB)
#define PHI_SMEM  (PHI_B_LO + 4 * TSB)   /* 83968 */

__global__ __launch_bounds__(256, 2)
void phi_kernel(const float* __restrict__ Q, const float* __restrict__ K)
{
    extern __shared__ char smem[];
    const uint32_t sb = smem_u32(smem);
    const int tid = threadIdx.x, wid = tid >> 5, lane = tid & 31;
    const bool isq = blockIdx.x < 512;
    const int tile = blockIdx.x & 511;
    const int row0 = tile * 64;
    const float* X = isq ? Q : K;
    const int m0 = (wid & 1) * 32, n0 = (wid >> 1) * 64, warpN = wid >> 1;

    float* h_sm    = (float*)smem;               // [64]
    float* rmax_sm = (float*)(smem + 256);       // [64]
    float* rmaxp   = (float*)(smem + 512);       // [64][4]
    float* wm_sm   = (float*)(smem + 1536);      // [2]
    float* bmax_s  = (float*)(smem + 1568);      // [1]
    float* w_sm    = (float*)(smem + 1600);      // [64]
    float* dbuf    = (float*)(smem + PHI_A_HI);  // [64][257]

    if (tid == 0) MBAR_INIT(sb + PHI_MBAR, 1);
    __syncthreads();

    float c[2][8][4];
#pragma unroll
    for (int mt = 0; mt < 2; mt++)
#pragma unroll
        for (int nt = 0; nt < 8; nt++)
#pragma unroll
            for (int q = 0; q < 4; q++) c[mt][nt][q] = 0.f;

    const int arow = tid >> 2, aq = tid & 3;
#pragma unroll
    for (int ck = 0; ck < 2; ck++) {
        if (tid == 0) {
            MBAR_EXPECT(sb + PHI_MBAR, 65536);
            BULK_G2S(sb + PHI_B_HI, g_omTH + (size_t)ck * 4 * TS, 32768, sb + PHI_MBAR);
            BULK_G2S(sb + PHI_B_LO, g_omTL + (size_t)ck * 4 * TS, 32768, sb + PHI_MBAR);
        }
        // A: load X chunk, scale, h partial, split hi/lo into swizzled tile
        const float4* xr = (const float4*)(X + (size_t)(row0 + arow) * DQK + ck * 64 + aq * 16);
        float hp = 0.f;
#pragma unroll
        for (int j = 0; j < 4; j++) {
            float4 v = xr[j];
            v.x *= INV_D4; v.y *= INV_D4; v.z *= INV_D4; v.w *= INV_D4;
            hp += v.x * v.x + v.y * v.y + v.z * v.z + v.w * v.w;
            uint32_t hwA, lwA, hwB, lwB;
            split_pair(v.x, v.y, hwA, lwA);
            split_pair(v.z, v.w, hwB, lwB);
            uint32_t off = swz((uint32_t)(arow * 128 + (aq * 16 + j * 4) * 2));
            *(uint2*)(smem + PHI_A_HI + off) = make_uint2(hwA, hwB);
            *(uint2*)(smem + PHI_A_LO + off) = make_uint2(lwA, lwB);
        }
        hp += __shfl_xor_sync(0xffffffffu, hp, 1);
        hp += __shfl_xor_sync(0xffffffffu, hp, 2);
        if ((lane & 3) == 0) {
            if (ck == 0) h_sm[arow] = 0.5f * hp;
            else         h_sm[arow] += 0.5f * hp;
        }
        MBAR_WAIT(sb + PHI_MBAR, ck & 1);
        __syncthreads();
        gemm_chunk(c, sb + PHI_A_HI, sb + PHI_A_LO, sb + PHI_B_HI, sb + PHI_B_LO,
                   lane, m0, n0);
        __syncthreads();
    }

    float rmx[2][2] = {{-3.0e38f, -3.0e38f}, {-3.0e38f, -3.0e38f}};
#pragma unroll
    for (int mt = 0; mt < 2; mt++)
#pragma unroll
        for (int nt = 0; nt < 8; nt++) {
            rmx[mt][0] = fmaxf(rmx[mt][0], fmaxf(c[mt][nt][0], c[mt][nt][1]));
            rmx[mt][1] = fmaxf(rmx[mt][1], fmaxf(c[mt][nt][2], c[mt][nt][3]));
        }
#pragma unroll
    for (int mt = 0; mt < 2; mt++)
#pragma unroll
        for (int hh = 0; hh < 2; hh++) {
            float v = rmx[mt][hh];
            v = fmaxf(v, __shfl_xor_sync(0xffffffffu, v, 1));
            v = fmaxf(v, __shfl_xor_sync(0xffffffffu, v, 2));
            rmx[mt][hh] = v;
        }
    {
        int g = lane >> 2;
        if ((lane & 3) == 0) {
            rmaxp[(m0 + g) * 4 + warpN]      = rmx[0][0];
            rmaxp[(m0 + g + 8) * 4 + warpN]  = rmx[0][1];
            rmaxp[(m0 + 16 + g) * 4 + warpN] = rmx[1][0];
            rmaxp[(m0 + 24 + g) * 4 + warpN] = rmx[1][1];
        }
    }
    __syncthreads();
    if (tid < 64) {
        float rm = fmaxf(fmaxf(rmaxp[tid * 4], rmaxp[tid * 4 + 1]),
                         fmaxf(rmaxp[tid * 4 + 2], rmaxp[tid * 4 + 3]));
        rmax_sm[tid] = rm;
        if (!isq) {
            g_rowmax[row0 + tid] = rm;
            float bm = warpMax(rm);
            if (lane == 0) wm_sm[wid] = bm;
        }
    }
    __syncthreads();
    if (!isq) {
        if (tid == 0) {
            float bm = fmaxf(wm_sm[0], wm_sm[1]);
            bmax_s[0] = bm;
            g_bmax[tile] = bm;
            atomicMax(&g_segmax[tile >> 3], f2o(bm));
        }
        __syncthreads();
        if (tid < 64) w_sm[tid] = __expf(rmax_sm[tid] - bmax_s[0]);
    }

    if (isq) {
        // Qp: exp + eps + scale -> swizzled tiles [rt][kt]
        int g = lane >> 2, j = lane & 3;
#pragma unroll
        for (int mt = 0; mt < 2; mt++) {
            int r0 = m0 + mt * 16 + g, r1 = r0 + 8;
            float hm0 = h_sm[r0] + rmax_sm[r0];
            float hm1 = h_sm[r1] + rmax_sm[r1];
#pragma unroll
            for (int nt = 0; nt < 8; nt++) {
                int col = n0 + nt * 8 + j * 2;
                float v0 = (__expf(c[mt][nt][0] - hm0) + EPS_PHI) * INV_SQRT_M;
                float v1 = (__expf(c[mt][nt][1] - hm0) + EPS_PHI) * INV_SQRT_M;
                float v2 = (__expf(c[mt][nt][2] - hm1) + EPS_PHI) * INV_SQRT_M;
                float v3 = (__expf(c[mt][nt][3] - hm1) + EPS_PHI) * INV_SQRT_M;
                int kt = col >> 6, cl = col & 63;
                size_t base = ((size_t)tile * 4 + kt) * TS;
                uint32_t hw, lw;
                split_pair(v0, v1, hw, lw);
                uint32_t o0 = swz((uint32_t)(r0 * 128 + cl * 2)) >> 1;
                *(uint32_t*)&g_QpH[base + o0] = hw;
                *(uint32_t*)&g_QpL[base + o0] = lw;
                split_pair(v2, v3, hw, lw);
                uint32_t o1 = swz((uint32_t)(r1 * 128 + cl * 2)) >> 1;
                *(uint32_t*)&g_QpH[base + o1] = hw;
                *(uint32_t*)&g_QpL[base + o1] = lw;
            }
        }
    } else {
        // Kp0 -> dbuf, transposed swizzled tile stores [tt][ft] + W partial
        int g = lane >> 2;
        float e[2][8][4];
#pragma unroll
        for (int mt = 0; mt < 2; mt++) {
            int r0 = m0 + mt * 16 + g, r1 = r0 + 8;
            float hm0 = h_sm[r0] + rmax_sm[r0];
            float hm1 = h_sm[r1] + rmax_sm[r1];
#pragma unroll
            for (int nt = 0; nt < 8; nt++) {
                e[mt][nt][0] = __expf(c[mt][nt][0] - hm0);
                e[mt][nt][1] = __expf(c[mt][nt][1] - hm0);
                e[mt][nt][2] = __expf(c[mt][nt][2] - hm1);
                e[mt][nt][3] = __expf(c[mt][nt][3] - hm1);
            }
        }
        __syncthreads();
        frag_to_dbuf<257>(dbuf, e, lane, m0, n0);
        __syncthreads();
#pragma unroll 4
        for (int i = 0; i < 32; i++) {
            int f = i * 256 + tid, feat = f >> 5, tp = (f & 31) * 2;
            uint32_t hw, lw;
            split_pair(dbuf[tp * 257 + feat], dbuf[(tp + 1) * 257 + feat], hw, lw);
            int ft = feat >> 6, fl = feat & 63;
            size_t base = ((size_t)tile * 4 + ft) * TS;
            uint32_t off = swz((uint32_t)(fl * 128 + tp * 2)) >> 1;
            *(uint32_t*)&g_KpTH[base + off] = hw;
            *(uint32_t*)&g_KpTL[base + off] = lw;
        }
        float s = 0.f;
#pragma unroll 4
        for (int t = 0; t < 64; t++) s += dbuf[t * 257 + tid] * w_sm[t];
        g_W[tile * 256 + tid] = s;
    }
}

// ---------------- kv: tile 256m x 128v, 512 thr, depth-2 bulk pipeline ----------------
#define KV_AH   0
#define KV_AL   32768
#define KV_BH   65536
#define KV_BL   81920
#define KV_STG  98304
#define KV_MB0  196608
#define KV_MB1  196616
#define KV_SV   196640
#define KV_SMEM 197664

__global__ __launch_bounds__(512, 1)
void kv_kernel()
{
    extern __shared__ char smem[];
    const uint32_t sb = smem_u32(smem);
    const int tid = threadIdx.x, wid = tid >> 5, lane = tid & 31;
    const int b = blockIdx.x >> 1, vh = blockIdx.x & 1;
    const int v0 = vh * 128;
    const int m0 = (wid & 7) * 32, n0 = (wid >> 3) * 64;

    if (tid == 0) { MBAR_INIT(sb + KV_MB0, 1); MBAR_INIT(sb + KV_MB1, 1); }
    __syncthreads();

    float c[2][8][4];
#pragma unroll
    for (int mt = 0; mt < 2; mt++)
#pragma unroll
        for (int nt = 0; nt < 8; nt++)
#pragma unroll
            for (int q = 0; q < 4; q++) c[mt][nt][q] = 0.f;

    if (tid == 0) {
        size_t tt = (size_t)b * 8;
        MBAR_EXPECT(sb + KV_MB0, 98304);
        BULK_G2S(sb + KV_AH, g_KpTH + tt * 4 * TS, 32768, sb + KV_MB0);
        BULK_G2S(sb + KV_AL, g_KpTL + tt * 4 * TS, 32768, sb + KV_MB0);
        BULK_G2S(sb + KV_BH, g_VTH + (tt * 4 + vh * 2) * TS, 16384, sb + KV_MB0);
        BULK_G2S(sb + KV_BL, g_VTL + (tt * 4 + vh * 2) * TS, 16384, sb + KV_MB0);
    }
    for (int ch = 0; ch < 8; ch++) {
        if (ch < 7 && tid == 0) {
            uint32_t s1 = sb + ((ch + 1) & 1) * KV_STG;
            uint32_t mb = sb + (((ch + 1) & 1) ? KV_MB1 : KV_MB0);
            size_t tt = (size_t)b * 8 + ch + 1;
            MBAR_EXPECT(mb, 98304);
            BULK_G2S(s1 + KV_AH, g_KpTH + tt * 4 * TS, 32768, mb);
            BULK_G2S(s1 + KV_AL, g_KpTL + tt * 4 * TS, 32768, mb);
            BULK_G2S(s1 + KV_BH, g_VTH + (tt * 4 + vh * 2) * TS, 16384, mb);
            BULK_G2S(s1 + KV_BL, g_VTL + (tt * 4 + vh * 2) * TS, 16384, mb);
        }
        MBAR_WAIT(sb + ((ch & 1) ? KV_MB1 : KV_MB0), (ch >> 1) & 1);
        uint32_t s0 = sb + (ch & 1) * KV_STG;
        gemm_chunk(c, s0 + KV_AH, s0 + KV_AL, s0 + KV_BH, s0 + KV_BL, lane, m0, n0);
        __syncthreads();
    }

    // epilogue: KVT tiles [b][kt][vt] = (D[m][v] + eps*SV[v]) / sqrt(m)
    float* dbuf = (float*)smem;                    // [256][129]
    float* sv   = (float*)(smem + KV_SV);          // [128]
    frag_to_dbuf<129>(dbuf, c, lane, m0, n0);
    if (tid < 128) {
        const float* P = g_SVp + (size_t)(8 * b) * 256 + v0 + tid;
        float s = 0.f;
#pragma unroll
        for (int t = 0; t < 8; t++) s += P[t * 256];
        sv[tid] = s * EPS_PHI;
    }
    __syncthreads();
#pragma unroll 4
    for (int i = 0; i < 32; i++) {
        int f = i * 512 + tid, v = f >> 7, mp = (f & 127) * 2;
        float base = sv[v];
        float v0f = (dbuf[mp * 129 + v] + base) * INV_SQRT_M;
        float v1f = (dbuf[(mp + 1) * 129 + v] + base) * INV_SQRT_M;
        uint32_t hw, lw;
        split_pair(v0f, v1f, hw, lw);
        int kt = mp >> 6, vt = (v0 >> 6) + (v >> 6);
        size_t tbase = ((size_t)b * 16 + kt * 4 + vt) * TS;
        uint32_t off = swz((uint32_t)((v & 63) * 128 + (mp & 63) * 2)) >> 1;
        *(uint32_t*)&g_KVTH[tbase + off] = hw;
        *(uint32_t*)&g_KVTL[tbase + off] = lw;
    }
}

// ---------------- out: tile 128row x 256v, 512 thr, depth-2 bulk pipeline, norm fused ----------------
#define OU_AH   0
#define OU_AL   16384
#define OU_BH   32768
#define OU_BL   65536
#define OU_STG  98304
#define OU_MB0  196608
#define OU_MB1  196616
#define OU_KSUM 196640
#define OU_WT   197664
#define OU_NRM  197696
#define OU_SMEM 198208

__global__ __launch_bounds__(512, 1)
void out_kernel(float* __restrict__ Out)
{
    extern __shared__ char smem[];
    const uint32_t sb = smem_u32(smem);
    const int tid = threadIdx.x, wid = tid >> 5, lane = tid & 31;
    const int b = blockIdx.x >> 2, rt = blockIdx.x & 3;
    const int row0 = b * NPER + rt * 128;
    const int rt0 = row0 >> 6;
    const int m0 = (wid & 3) * 32, n0 = (wid >> 2) * 64;
    float* ksum = (float*)(smem + OU_KSUM);        // [256]
    float* wtp  = (float*)(smem + OU_WT);          // [8]

    if (tid == 0) { MBAR_INIT(sb + OU_MB0, 1); MBAR_INIT(sb + OU_MB1, 1); }
    __syncthreads();

    if (tid < 8) wtp[tid] = __expf(g_bmax[b * 8 + tid] - o2f(g_segmax[b]));
    __syncthreads();
    if (tid < 256) {
        float s = 0.f;
#pragma unroll
        for (int t = 0; t < 8; t++) s += g_W[(size_t)(8 * b + t) * 256 + tid] * wtp[t];
        ksum[tid] = (s + 512.0f * EPS_PHI) * INV_SQRT_M;
    }

    float c[2][8][4];
#pragma unroll
    for (int mt = 0; mt < 2; mt++)
#pragma unroll
        for (int nt = 0; nt < 8; nt++)
#pragma unroll
            for (int q = 0; q < 4; q++) c[mt][nt][q] = 0.f;

    const int qrow = tid >> 2, qoff = (tid & 3) * 16;
    float qd = 0.f;

    if (tid == 0) {
        MBAR_EXPECT(sb + OU_MB0, 98304);
        BULK_G2S(sb + OU_AH,       g_QpH + ((size_t)rt0 * 4 + 0) * TS, 8192, sb + OU_MB0);
        BULK_G2S(sb + OU_AH + TSB, g_QpH + ((size_t)(rt0 + 1) * 4 + 0) * TS, 8192, sb + OU_MB0);
        BULK_G2S(sb + OU_AL,       g_QpL + ((size_t)rt0 * 4 + 0) * TS, 8192, sb + OU_MB0);
        BULK_G2S(sb + OU_AL + TSB, g_QpL + ((size_t)(rt0 + 1) * 4 + 0) * TS, 8192, sb + OU_MB0);
        BULK_G2S(sb + OU_BH, g_KVTH + ((size_t)b * 16 + 0) * TS, 32768, sb + OU_MB0);
        BULK_G2S(sb + OU_BL, g_KVTL + ((size_t)b * 16 + 0) * TS, 32768, sb + OU_MB0);
    }
    for (int ch = 0; ch < 4; ch++) {
        if (ch < 3 && tid == 0) {
            uint32_t s1 = sb + ((ch + 1) & 1) * OU_STG;
            uint32_t mb = sb + (((ch + 1) & 1) ? OU_MB1 : OU_MB0);
            int kt = ch + 1;
            MBAR_EXPECT(mb, 98304);
            BULK_G2S(s1 + OU_AH,       g_QpH + ((size_t)rt0 * 4 + kt) * TS, 8192, mb);
            BULK_G2S(s1 + OU_AH + TSB, g_QpH + ((size_t)(rt0 + 1) * 4 + kt) * TS, 8192, mb);
            BULK_G2S(s1 + OU_AL,       g_QpL + ((size_t)rt0 * 4 + kt) * TS, 8192, mb);
            BULK_G2S(s1 + OU_AL + TSB, g_QpL + ((size_t)(rt0 + 1) * 4 + kt) * TS, 8192, mb);
            BULK_G2S(s1 + OU_BH, g_KVTH + ((size_t)b * 16 + kt * 4) * TS, 32768, mb);
            BULK_G2S(s1 + OU_BL, g_KVTL + ((size_t)b * 16 + kt * 4) * TS, 32768, mb);
        }
        MBAR_WAIT(sb + ((ch & 1) ? OU_MB1 : OU_MB0), (ch >> 1) & 1);
        uint32_t s0 = sb + (ch & 1) * OU_STG;
        // qdot partial from staged A (swizzled) against ksum
        {
            const char* AH = smem + (ch & 1) * OU_STG + OU_AH;
            const char* AL = smem + (ch & 1) * OU_STG + OU_AL;
            uint32_t tb = (uint32_t)(qrow >> 6) * TSB + (uint32_t)(qrow & 63) * 128u;
            uint32_t rx = (uint32_t)(qrow & 7) << 4;
            int k0 = ch * 64;
            float qp = 0.f;
#pragma unroll
            for (int jq = 0; jq < 4; jq++) {
                uint32_t o = tb + (((uint32_t)(qoff + jq * 4) * 2) ^ rx);
                uint2 h2 = *(const uint2*)(AH + o);
                uint2 l2 = *(const uint2*)(AL + o);
                const uint16_t* hp = (const uint16_t*)&h2;
                const uint16_t* lp = (const uint16_t*)&l2;
#pragma unroll
                for (int j = 0; j < 4; j++)
                    qp += from2(hp[j], lp[j]) * ksum[k0 + qoff + jq * 4 + j];
            }
            qd += qp;
        }
        gemm_chunk(c, s0 + OU_AH, s0 + OU_AL, s0 + OU_BH, s0 + OU_BL, lane, m0, n0);
        __syncthreads();
    }

    qd += __shfl_xor_sync(0xffffffffu, qd, 1);
    qd += __shfl_xor_sync(0xffffffffu, qd, 2);

    float* dbuf   = (float*)smem;                  // [128][257]
    float* nrm_sm = (float*)(smem + OU_NRM);       // [128]
    frag_to_dbuf<257>(dbuf, c, lane, m0, n0);
    if ((tid & 3) == 0) nrm_sm[qrow] = 1.0f / (qd + EPS_NORM);
    __syncthreads();
#pragma unroll
    for (int i = 0; i < 16; i++) {
        int f = i * 512 + tid, rr = f >> 6, c4 = (f & 63) * 4;
        float inv = nrm_sm[rr];
        float4 o = make_float4(dbuf[rr * 257 + c4] * inv, dbuf[rr * 257 + c4 + 1] * inv,
                               dbuf[rr * 257 + c4 + 2] * inv, dbuf[rr * 257 + c4 + 3] * inv);
        *(float4*)(Out + (size_t)(row0 + rr) * DV + c4) = o;
    }
}

// ---------------- launch ----------------
extern "C" void kernel_launch(void* const* d_in, const int* in_sizes, int n_in,
                              void* d_out, int out_size)
{
    (void)in_sizes; (void)n_in; (void)out_size;
    const float* Q     = (const float*)d_in[0];
    const float* K     = (const float*)d_in[1];
    const float* V     = (const float*)d_in[2];
    const float* omega = (const float*)d_in[3];
    float* Out = (float*)d_out;

    cudaFuncSetAttribute(omT_kernel,  cudaFuncAttributeMaxDynamicSharedMemorySize, OMT_SMEM);
    cudaFuncSetAttribute(vT_kernel,   cudaFuncAttributeMaxDynamicSharedMemorySize, VT_SMEM);
    cudaFuncSetAttribute(phi_kernel,  cudaFuncAttributeMaxDynamicSharedMemorySize, PHI_SMEM);
    cudaFuncSetAttribute(kv_kernel,   cudaFuncAttributeMaxDynamicSharedMemorySize, KV_SMEM);
    cudaFuncSetAttribute(out_kernel,  cudaFuncAttributeMaxDynamicSharedMemorySize, OU_SMEM);

    omT_kernel<<<4, 256, OMT_SMEM>>>(omega);
    phi_kernel<<<1024, 256, PHI_SMEM>>>(Q, K);
    vT_kernel<<<dim3(512, 2), 256, VT_SMEM>>>(V);
    kv_kernel<<<128, 512, KV_SMEM>>>();
    out_kernel<<<256, 512, OU_SMEM>>>(Out);
}